// round 11
// baseline (speedup 1.0000x reference)
#include <cuda_runtime.h>
#include <cstdint>
#include <math.h>

#define Bc 2
#define Nc 2048
#define Dc 1024
#define Hc 16
#define E3 192   // 3*DH; chunk order k(0:64), q(64:128), v(128:192)

__device__ float g_kqv[Bc * Hc * Nc * E3];   // [b,h,n,192] (tf32-rounded)
__device__ float g_sa[Bc * Nc * Dc];         // [b,n,d]    (tf32-rounded)
__device__ float g_WkT[Hc * E3 * Dc];        // W_kqv as [c][k], tf32-rounded
__device__ float g_x32[Bc * Nc * Dc];        // x, tf32-rounded
__device__ float g_Wp32[Dc * Dc];            // W_proj, tf32-rounded

__device__ __forceinline__ uint32_t smem_to_u32(const void* p) {
    uint32_t a;
    asm("{ .reg .u64 t; cvta.to.shared.u64 t, %1; cvt.u32.u64 %0, t; }"
        : "=r"(a) : "l"(p));
    return a;
}
__device__ __forceinline__ float to_tf32(float v) {
    float r;
    asm("cvt.rna.tf32.f32 %0, %1;" : "=f"(r) : "f"(v));
    return r;
}
__device__ __forceinline__ float4 to_tf32_4(float4 v) {
    float4 r;
    r.x = to_tf32(v.x); r.y = to_tf32(v.y); r.z = to_tf32(v.z); r.w = to_tf32(v.w);
    return r;
}
__device__ __forceinline__ void mma_tf32(float* c, const uint32_t* a, const uint32_t* b) {
    asm volatile(
        "mma.sync.aligned.m16n8k8.row.col.f32.tf32.tf32.f32 "
        "{%0,%1,%2,%3}, {%4,%5,%6,%7}, {%8,%9}, {%0,%1,%2,%3};"
        : "+f"(c[0]), "+f"(c[1]), "+f"(c[2]), "+f"(c[3])
        : "r"(a[0]), "r"(a[1]), "r"(a[2]), "r"(a[3]), "r"(b[0]), "r"(b[1]));
}
#define CP16(dst_u32, src_ptr) \
    asm volatile("cp.async.cg.shared.global [%0], [%1], 16;" \
        :: "r"(dst_u32), "l"(src_ptr))
#define CP_COMMIT() asm volatile("cp.async.commit_group;" ::: "memory")
#define CP_WAIT1()  asm volatile("cp.async.wait_group 1;" ::: "memory")
#define CP_WAIT0()  asm volatile("cp.async.wait_group 0;" ::: "memory")

// ---------------------------------------------------------------------------
// Pre-passes: round inputs to tf32 once.
// ---------------------------------------------------------------------------
__global__ __launch_bounds__(256) void round_x(const float* __restrict__ x)
{
    const int i = (blockIdx.x * 256 + threadIdx.x) * 4;
    float4 v = *(const float4*)&x[i];
    *(float4*)&g_x32[i] = to_tf32_4(v);
}
__global__ __launch_bounds__(256) void round_wp(const float* __restrict__ Wp)
{
    const int i = (blockIdx.x * 256 + threadIdx.x) * 4;
    float4 v = *(const float4*)&Wp[i];
    *(float4*)&g_Wp32[i] = to_tf32_4(v);
}
// Transpose W_kqv [H][D][E3] -> g_WkT [H*E3][D], tf32-rounded.
__global__ __launch_bounds__(256) void transpose_wk(const float* __restrict__ Wk)
{
    __shared__ float tile[32][33];
    const int e0 = blockIdx.x * 32, k0 = blockIdx.y * 32, h = blockIdx.z;
    const float* src = Wk + (size_t)h * Dc * E3;
    float* dst = g_WkT + (size_t)h * E3 * Dc;
    const int tx = threadIdx.x & 31, ty0 = threadIdx.x >> 5;
    #pragma unroll
    for (int i = 0; i < 4; i++) {
        int ty = ty0 + i * 8;
        tile[ty][tx] = src[(size_t)(k0 + ty) * E3 + e0 + tx];
    }
    __syncthreads();
    #pragma unroll
    for (int i = 0; i < 4; i++) {
        int ty = ty0 + i * 8;
        dst[(size_t)(e0 + ty) * Dc + k0 + tx] = to_tf32(tile[tx][ty]);
    }
}

// ---------------------------------------------------------------------------
// tf32 mma.sync GEMM: 128x128 CTA tile, 4 warps (2x2), warp tile 64x64.
// 2-stage cp.async + DOUBLE-BUFFERED FRAGMENT REGISTERS: load kk+1's A/B
// fragments before issuing kk's MMAs so the tensor queue never starves on LDS.
// ---------------------------------------------------------------------------
#define GSMP 36
#define GSTG 9216                 // floats per stage (A 4608 + B 4608)
#define GSMEM (2 * GSTG * 4)      // 73728 B
template<bool KQV>
__global__ __launch_bounds__(128) void gemm_mma(
    const float* __restrict__ bias, float* __restrict__ outp)
{
    const float* __restrict__ A    = KQV ? (const float*)g_x32 : (const float*)g_sa;
    const float* __restrict__ Bmat = KQV ? (const float*)g_WkT : (const float*)g_Wp32;

    extern __shared__ float sm[];
    const uint32_t su = smem_to_u32(sm);
    const int t = threadIdx.x;
    const int lane = t & 31;
    const int warp = t >> 5;           // 0..3
    const int mbase = (warp >> 1) * 64;
    const int nbase = (warp & 1) * 64;
    const int grp = lane >> 2;
    const int ctg = lane & 3;
    const int c0 = blockIdx.x * 128;
    const int r0 = blockIdx.y * 128;

    auto issue_slab = [&](int s, int buf) {
        const int k0 = s * 32;
        #pragma unroll
        for (int it = 0; it < 8; it++) {
            const int task = it * 128 + t;
            const int row = task >> 3, i4 = (task & 7) * 4;
            CP16(su + (uint32_t)(buf * GSTG + row * GSMP + i4) * 4,
                 &A[(size_t)(r0 + row) * Dc + k0 + i4]);
            CP16(su + (uint32_t)(buf * GSTG + 4608 + row * GSMP + i4) * 4,
                 &Bmat[(size_t)(c0 + row) * Dc + k0 + i4]);
        }
    };

    issue_slab(0, 0); CP_COMMIT();
    issue_slab(1, 1); CP_COMMIT();

    float C[4][8][4];
    #pragma unroll
    for (int i = 0; i < 4; i++)
        #pragma unroll
        for (int j = 0; j < 8; j++)
            #pragma unroll
            for (int k = 0; k < 4; k++) C[i][j][k] = 0.f;

    for (int s = 0; s < 32; s++) {
        if (s == 31) { CP_WAIT0(); } else { CP_WAIT1(); }
        __syncthreads();
        const float* As = sm + (s & 1) * GSTG;
        const float* Bs = As + 4608;

        uint32_t af[2][4][4], bf[2][8][2];
        // preload fragments for kk = 0
        {
            const int kof = ctg;
            #pragma unroll
            for (int tm = 0; tm < 4; tm++) {
                const int m = mbase + tm * 16 + grp;
                af[0][tm][0] = __float_as_uint(As[m * GSMP + kof]);
                af[0][tm][1] = __float_as_uint(As[(m + 8) * GSMP + kof]);
                af[0][tm][2] = __float_as_uint(As[m * GSMP + kof + 4]);
                af[0][tm][3] = __float_as_uint(As[(m + 8) * GSMP + kof + 4]);
            }
            #pragma unroll
            for (int tn = 0; tn < 8; tn++) {
                const int n = nbase + tn * 8 + grp;
                bf[0][tn][0] = __float_as_uint(Bs[n * GSMP + kof]);
                bf[0][tn][1] = __float_as_uint(Bs[n * GSMP + kof + 4]);
            }
        }
        #pragma unroll
        for (int kk = 0; kk < 4; kk++) {
            const int cur = kk & 1, nxt = cur ^ 1;
            if (kk < 3) {   // prefetch next kk's fragments before current MMAs
                const int kof = (kk + 1) * 8 + ctg;
                #pragma unroll
                for (int tm = 0; tm < 4; tm++) {
                    const int m = mbase + tm * 16 + grp;
                    af[nxt][tm][0] = __float_as_uint(As[m * GSMP + kof]);
                    af[nxt][tm][1] = __float_as_uint(As[(m + 8) * GSMP + kof]);
                    af[nxt][tm][2] = __float_as_uint(As[m * GSMP + kof + 4]);
                    af[nxt][tm][3] = __float_as_uint(As[(m + 8) * GSMP + kof + 4]);
                }
                #pragma unroll
                for (int tn = 0; tn < 8; tn++) {
                    const int n = nbase + tn * 8 + grp;
                    bf[nxt][tn][0] = __float_as_uint(Bs[n * GSMP + kof]);
                    bf[nxt][tn][1] = __float_as_uint(Bs[n * GSMP + kof + 4]);
                }
            }
            #pragma unroll
            for (int tn = 0; tn < 8; tn++)
                #pragma unroll
                for (int tm = 0; tm < 4; tm++)
                    mma_tf32(C[tm][tn], af[cur][tm], bf[cur][tn]);
        }
        __syncthreads();
        if (s + 2 < 32) issue_slab(s + 2, s & 1);
        CP_COMMIT();
    }

    // Epilogue: C rows grp/grp+8, cols 2*ctg, 2*ctg+1
    #pragma unroll
    for (int tm = 0; tm < 4; tm++) {
        #pragma unroll
        for (int tn = 0; tn < 8; tn++) {
            const int c = c0 + nbase + tn * 8 + ctg * 2;
            const float bs0 = bias[c], bs1 = bias[c + 1];
            #pragma unroll
            for (int half = 0; half < 2; half++) {
                const int row = r0 + mbase + tm * 16 + grp + half * 8;
                float2 o;
                o.x = C[tm][tn][half * 2 + 0] + bs0;
                o.y = C[tm][tn][half * 2 + 1] + bs1;
                if (KQV) {
                    o.x = to_tf32(o.x); o.y = to_tf32(o.y);
                    const int h = c / E3;
                    const int e = c - h * E3;
                    const int b = row >> 11, n = row & 2047;
                    *(float2*)&g_kqv[(((size_t)(b * Hc + h)) * Nc + n) * E3 + e] = o;
                } else {
                    *(float2*)&outp[(size_t)row * Dc + c] = o;
                }
            }
        }
    }
}

// ---------------------------------------------------------------------------
// Attention (unchanged, known good): flash, 64x64 tile, 4 warps x 16 rows.
// ---------------------------------------------------------------------------
#define ATTN_SMEM 53248
__global__ __launch_bounds__(128) void attn_mma()
{
    extern __shared__ float sm[];
    float* Ks  = sm;           // stride 68
    float* QPs = sm + 4352;    // stride 68 (Q staged, then P per-warp bands)
    float* Vs  = sm + 8704;    // stride 72

    const int t = threadIdx.x;
    const int lane = t & 31, warp = t >> 5;
    const int grp = lane >> 2, ctg = lane & 3;
    const int mb = warp * 16;
    const int bh = blockIdx.y;
    const int b = bh >> 4, h = bh & 15;
    const int qt = (int)gridDim.x - 1 - (int)blockIdx.x;   // heavy blocks first
    const int q0 = qt * 64;
    const float* base = g_kqv + (size_t)bh * Nc * E3;

    #pragma unroll
    for (int it = 0; it < 8; it++) {
        int task = it * 128 + t;
        int c = task >> 4, d4 = (task & 15) * 4;
        float4 v = *(const float4*)&base[(size_t)(q0 + c) * E3 + 64 + d4];
        v.x *= 0.125f; v.y *= 0.125f; v.z *= 0.125f; v.w *= 0.125f;
        *(float4*)&QPs[c * 68 + d4] = v;
    }
    __syncthreads();
    uint32_t qf[8][4];
    #pragma unroll
    for (int kk = 0; kk < 8; kk++) {
        qf[kk][0] = __float_as_uint(QPs[(mb + grp) * 68 + kk * 8 + ctg]);
        qf[kk][1] = __float_as_uint(QPs[(mb + grp + 8) * 68 + kk * 8 + ctg]);
        qf[kk][2] = __float_as_uint(QPs[(mb + grp) * 68 + kk * 8 + ctg + 4]);
        qf[kk][3] = __float_as_uint(QPs[(mb + grp + 8) * 68 + kk * 8 + ctg + 4]);
    }

    float OC[8][4];
    #pragma unroll
    for (int i = 0; i < 8; i++)
        #pragma unroll
        for (int j = 0; j < 4; j++) OC[i][j] = 0.f;
    float m0 = -1e30f, m1 = -1e30f, l0 = 0.f, l1 = 0.f;

    for (int kt = 0; kt <= qt; kt++) {
        const int k0 = kt * 64;
        __syncthreads();
        #pragma unroll
        for (int it = 0; it < 8; it++) {
            int task = it * 128 + t;
            int c = task >> 4, d4 = (task & 15) * 4;
            float4 v = *(const float4*)&base[(size_t)(k0 + c) * E3 + d4];
            *(float4*)&Ks[c * 68 + d4] = v;
        }
        #pragma unroll
        for (int it = 0; it < 8; it++) {
            int task = it * 128 + t;
            int c = task >> 4, d4 = (task & 15) * 4;
            float4 v = *(const float4*)&base[(size_t)(k0 + c) * E3 + 128 + d4];
            *(float4*)&Vs[c * 72 + d4] = v;
        }
        __syncthreads();

        float SC[8][4];
        #pragma unroll
        for (int i = 0; i < 8; i++)
            #pragma unroll
            for (int j = 0; j < 4; j++) SC[i][j] = 0.f;
        #pragma unroll
        for (int kk = 0; kk < 8; kk++) {
            #pragma unroll
            for (int nt = 0; nt < 8; nt++) {
                uint32_t bf[2];
                bf[0] = __float_as_uint(Ks[(nt * 8 + grp) * 68 + kk * 8 + ctg]);
                bf[1] = __float_as_uint(Ks[(nt * 8 + grp) * 68 + kk * 8 + ctg + 4]);
                mma_tf32(SC[nt], qf[kk], bf);
            }
        }

        if (kt == qt) {
            const int r0l = mb + grp, r1l = mb + grp + 8;
            #pragma unroll
            for (int nt = 0; nt < 8; nt++) {
                const int col = nt * 8 + 2 * ctg;
                if (col > r0l)     SC[nt][0] = -1e30f;
                if (col + 1 > r0l) SC[nt][1] = -1e30f;
                if (col > r1l)     SC[nt][2] = -1e30f;
                if (col + 1 > r1l) SC[nt][3] = -1e30f;
            }
        }

        float tm0 = -1e30f, tm1 = -1e30f;
        #pragma unroll
        for (int nt = 0; nt < 8; nt++) {
            tm0 = fmaxf(tm0, fmaxf(SC[nt][0], SC[nt][1]));
            tm1 = fmaxf(tm1, fmaxf(SC[nt][2], SC[nt][3]));
        }
        tm0 = fmaxf(tm0, __shfl_xor_sync(0xffffffffu, tm0, 1));
        tm0 = fmaxf(tm0, __shfl_xor_sync(0xffffffffu, tm0, 2));
        tm1 = fmaxf(tm1, __shfl_xor_sync(0xffffffffu, tm1, 1));
        tm1 = fmaxf(tm1, __shfl_xor_sync(0xffffffffu, tm1, 2));
        const float mn0 = fmaxf(m0, tm0), mn1 = fmaxf(m1, tm1);
        const float corr0 = __expf(m0 - mn0), corr1 = __expf(m1 - mn1);
        m0 = mn0; m1 = mn1;
        float s0 = 0.f, s1 = 0.f;
        #pragma unroll
        for (int nt = 0; nt < 8; nt++) {
            SC[nt][0] = __expf(SC[nt][0] - mn0); s0 += SC[nt][0];
            SC[nt][1] = __expf(SC[nt][1] - mn0); s0 += SC[nt][1];
            SC[nt][2] = __expf(SC[nt][2] - mn1); s1 += SC[nt][2];
            SC[nt][3] = __expf(SC[nt][3] - mn1); s1 += SC[nt][3];
        }
        s0 += __shfl_xor_sync(0xffffffffu, s0, 1);
        s0 += __shfl_xor_sync(0xffffffffu, s0, 2);
        s1 += __shfl_xor_sync(0xffffffffu, s1, 1);
        s1 += __shfl_xor_sync(0xffffffffu, s1, 2);
        l0 = l0 * corr0 + s0;
        l1 = l1 * corr1 + s1;
        #pragma unroll
        for (int nt = 0; nt < 8; nt++) {
            OC[nt][0] *= corr0; OC[nt][1] *= corr0;
            OC[nt][2] *= corr1; OC[nt][3] *= corr1;
        }

        #pragma unroll
        for (int nt = 0; nt < 8; nt++) {
            float2 p0, p1;
            p0.x = to_tf32(SC[nt][0]); p0.y = to_tf32(SC[nt][1]);
            p1.x = to_tf32(SC[nt][2]); p1.y = to_tf32(SC[nt][3]);
            *(float2*)&QPs[(mb + grp) * 68 + nt * 8 + 2 * ctg] = p0;
            *(float2*)&QPs[(mb + grp + 8) * 68 + nt * 8 + 2 * ctg] = p1;
        }
        __syncwarp();

        #pragma unroll
        for (int kk = 0; kk < 8; kk++) {
            uint32_t af[4];
            af[0] = __float_as_uint(QPs[(mb + grp) * 68 + kk * 8 + ctg]);
            af[1] = __float_as_uint(QPs[(mb + grp + 8) * 68 + kk * 8 + ctg]);
            af[2] = __float_as_uint(QPs[(mb + grp) * 68 + kk * 8 + ctg + 4]);
            af[3] = __float_as_uint(QPs[(mb + grp + 8) * 68 + kk * 8 + ctg + 4]);
            #pragma unroll
            for (int dt = 0; dt < 8; dt++) {
                uint32_t bf[2];
                bf[0] = __float_as_uint(Vs[(kk * 8 + ctg) * 72 + dt * 8 + grp]);
                bf[1] = __float_as_uint(Vs[(kk * 8 + ctg + 4) * 72 + dt * 8 + grp]);
                mma_tf32(OC[dt], af, bf);
            }
        }
    }

    const float inv0 = 1.f / l0, inv1 = 1.f / l1;
    const int r0g = b * Nc + q0 + mb + grp;
    #pragma unroll
    for (int dt = 0; dt < 8; dt++) {
        const int c = h * 64 + dt * 8 + 2 * ctg;
        float2 o0, o1;
        o0.x = to_tf32(OC[dt][0] * inv0); o0.y = to_tf32(OC[dt][1] * inv0);
        o1.x = to_tf32(OC[dt][2] * inv1); o1.y = to_tf32(OC[dt][3] * inv1);
        *(float2*)&g_sa[(size_t)r0g * Dc + c] = o0;
        *(float2*)&g_sa[(size_t)(r0g + 8) * Dc + c] = o1;
    }
}

extern "C" void kernel_launch(void* const* d_in, const int* in_sizes, int n_in,
                              void* d_out, int out_size)
{
    const float* x  = (const float*)d_in[0];
    const float* Wk = (const float*)d_in[1];
    const float* bk = (const float*)d_in[2];
    const float* Wp = (const float*)d_in[3];
    const float* bp = (const float*)d_in[4];
    float* out = (float*)d_out;

    cudaFuncSetAttribute((const void*)gemm_mma<true>,
                         cudaFuncAttributeMaxDynamicSharedMemorySize, GSMEM);
    cudaFuncSetAttribute((const void*)gemm_mma<false>,
                         cudaFuncAttributeMaxDynamicSharedMemorySize, GSMEM);
    cudaFuncSetAttribute((const void*)attn_mma,
                         cudaFuncAttributeMaxDynamicSharedMemorySize, ATTN_SMEM);

    round_x<<<4096, 256>>>(x);
    round_wp<<<1024, 256>>>(Wp);
    transpose_wk<<<dim3(6, 32, 16), 256>>>(Wk);

    gemm_mma<true><<<dim3(24, 32), 128, GSMEM>>>(bk, nullptr);

    attn_mma<<<dim3(32, 32), 128, ATTN_SMEM>>>();

    gemm_mma<false><<<dim3(8, 32), 128, GSMEM>>>(bp, out);
}

// round 13
// speedup vs baseline: 1.0756x; 1.0756x over previous
#include <cuda_runtime.h>
#include <cstdint>
#include <math.h>

#define Bc 2
#define Nc 2048
#define Dc 1024
#define Hc 16
#define E3 192   // 3*DH; chunk order k(0:64), q(64:128), v(128:192)

__device__ float g_kqv[Bc * Hc * Nc * E3];   // [b,h,n,192] (tf32-rounded)
__device__ float g_sa[Bc * Nc * Dc];         // [b,n,d]    (tf32-rounded)
__device__ float g_WkT[Hc * E3 * Dc];        // W_kqv as [c][k], tf32-rounded
__device__ float g_x32[Bc * Nc * Dc];        // x, tf32-rounded
__device__ float g_Wp32[Dc * Dc];            // W_proj, tf32-rounded

__device__ __forceinline__ uint32_t smem_to_u32(const void* p) {
    uint32_t a;
    asm("{ .reg .u64 t; cvta.to.shared.u64 t, %1; cvt.u32.u64 %0, t; }"
        : "=r"(a) : "l"(p));
    return a;
}
__device__ __forceinline__ float to_tf32(float v) {
    float r;
    asm("cvt.rna.tf32.f32 %0, %1;" : "=f"(r) : "f"(v));
    return r;
}
__device__ __forceinline__ float4 to_tf32_4(float4 v) {
    float4 r;
    r.x = to_tf32(v.x); r.y = to_tf32(v.y); r.z = to_tf32(v.z); r.w = to_tf32(v.w);
    return r;
}
__device__ __forceinline__ void mma_tf32(float* c, const uint32_t* a, const uint32_t* b) {
    asm volatile(
        "mma.sync.aligned.m16n8k8.row.col.f32.tf32.tf32.f32 "
        "{%0,%1,%2,%3}, {%4,%5,%6,%7}, {%8,%9}, {%0,%1,%2,%3};"
        : "+f"(c[0]), "+f"(c[1]), "+f"(c[2]), "+f"(c[3])
        : "r"(a[0]), "r"(a[1]), "r"(a[2]), "r"(a[3]), "r"(b[0]), "r"(b[1]));
}
#define CP16(dst_u32, src_ptr) \
    asm volatile("cp.async.cg.shared.global [%0], [%1], 16;" \
        :: "r"(dst_u32), "l"(src_ptr))
#define CP_COMMIT() asm volatile("cp.async.commit_group;" ::: "memory")
#define CP_WAIT1()  asm volatile("cp.async.wait_group 1;" ::: "memory")
#define CP_WAIT0()  asm volatile("cp.async.wait_group 0;" ::: "memory")

// ---------------------------------------------------------------------------
// Fused pre-pass: one launch does round(x), round(Wp), transpose+round(Wk).
// blocks [0,4096): x ; [4096,5120): Wp ; [5120,8192): Wk transpose.
// ---------------------------------------------------------------------------
__global__ __launch_bounds__(256) void prepass(
    const float* __restrict__ x, const float* __restrict__ Wp,
    const float* __restrict__ Wk)
{
    __shared__ float tile[32][33];
    const int bid = blockIdx.x;
    if (bid < 4096) {
        const int i = (bid * 256 + threadIdx.x) * 4;
        *(float4*)&g_x32[i] = to_tf32_4(*(const float4*)&x[i]);
    } else if (bid < 5120) {
        const int i = ((bid - 4096) * 256 + threadIdx.x) * 4;
        *(float4*)&g_Wp32[i] = to_tf32_4(*(const float4*)&Wp[i]);
    } else {
        const int idx = bid - 5120;          // 0..3071
        const int e0 = (idx % 6) * 32;
        const int k0 = ((idx / 6) % 32) * 32;
        const int h  = idx / 192;
        const float* src = Wk + (size_t)h * Dc * E3;
        float* dst = g_WkT + (size_t)h * E3 * Dc;
        const int tx = threadIdx.x & 31, ty0 = threadIdx.x >> 5;
        #pragma unroll
        for (int i = 0; i < 4; i++) {
            int ty = ty0 + i * 8;
            tile[ty][tx] = src[(size_t)(k0 + ty) * E3 + e0 + tx];
        }
        __syncthreads();
        #pragma unroll
        for (int i = 0; i < 4; i++) {
            int ty = ty0 + i * 8;
            dst[(size_t)(e0 + ty) * Dc + k0 + tx] = to_tf32(tile[tx][ty]);
        }
    }
}

// ---------------------------------------------------------------------------
// tf32 mma.sync GEMM (round-10 form, best known): 128x128 CTA tile, 4 warps,
// warp tile 64x64, 2-stage cp.async.
// ---------------------------------------------------------------------------
#define GSMP 36
#define GSTG 9216                 // floats per stage (A 4608 + B 4608)
#define GSMEM (2 * GSTG * 4)      // 73728 B
template<bool KQV>
__global__ __launch_bounds__(128) void gemm_mma(
    const float* __restrict__ bias, float* __restrict__ outp)
{
    const float* __restrict__ A    = KQV ? (const float*)g_x32 : (const float*)g_sa;
    const float* __restrict__ Bmat = KQV ? (const float*)g_WkT : (const float*)g_Wp32;

    extern __shared__ float sm[];
    const uint32_t su = smem_to_u32(sm);
    const int t = threadIdx.x;
    const int lane = t & 31;
    const int warp = t >> 5;           // 0..3
    const int mbase = (warp >> 1) * 64;
    const int nbase = (warp & 1) * 64;
    const int grp = lane >> 2;
    const int ctg = lane & 3;
    const int c0 = blockIdx.x * 128;
    const int r0 = blockIdx.y * 128;

    auto issue_slab = [&](int s, int buf) {
        const int k0 = s * 32;
        #pragma unroll
        for (int it = 0; it < 8; it++) {
            const int task = it * 128 + t;
            const int row = task >> 3, i4 = (task & 7) * 4;
            CP16(su + (uint32_t)(buf * GSTG + row * GSMP + i4) * 4,
                 &A[(size_t)(r0 + row) * Dc + k0 + i4]);
            CP16(su + (uint32_t)(buf * GSTG + 4608 + row * GSMP + i4) * 4,
                 &Bmat[(size_t)(c0 + row) * Dc + k0 + i4]);
        }
    };

    issue_slab(0, 0); CP_COMMIT();
    issue_slab(1, 1); CP_COMMIT();

    float C[4][8][4];
    #pragma unroll
    for (int i = 0; i < 4; i++)
        #pragma unroll
        for (int j = 0; j < 8; j++)
            #pragma unroll
            for (int k = 0; k < 4; k++) C[i][j][k] = 0.f;

    for (int s = 0; s < 32; s++) {
        if (s == 31) { CP_WAIT0(); } else { CP_WAIT1(); }
        __syncthreads();
        const float* As = sm + (s & 1) * GSTG;
        const float* Bs = As + 4608;
        #pragma unroll
        for (int kk = 0; kk < 4; kk++) {
            const int kof = kk * 8 + ctg;
            uint32_t af[4][4];
            #pragma unroll
            for (int tm = 0; tm < 4; tm++) {
                const int m = mbase + tm * 16 + grp;
                af[tm][0] = __float_as_uint(As[m * GSMP + kof]);
                af[tm][1] = __float_as_uint(As[(m + 8) * GSMP + kof]);
                af[tm][2] = __float_as_uint(As[m * GSMP + kof + 4]);
                af[tm][3] = __float_as_uint(As[(m + 8) * GSMP + kof + 4]);
            }
            #pragma unroll
            for (int tn = 0; tn < 8; tn++) {
                const int n = nbase + tn * 8 + grp;
                uint32_t bf[2];
                bf[0] = __float_as_uint(Bs[n * GSMP + kof]);
                bf[1] = __float_as_uint(Bs[n * GSMP + kof + 4]);
                #pragma unroll
                for (int tm = 0; tm < 4; tm++)
                    mma_tf32(C[tm][tn], af[tm], bf);
            }
        }
        __syncthreads();
        if (s + 2 < 32) issue_slab(s + 2, s & 1);
        CP_COMMIT();
    }

    // Epilogue: C rows grp/grp+8, cols 2*ctg, 2*ctg+1
    #pragma unroll
    for (int tm = 0; tm < 4; tm++) {
        #pragma unroll
        for (int tn = 0; tn < 8; tn++) {
            const int c = c0 + nbase + tn * 8 + ctg * 2;
            const float bs0 = bias[c], bs1 = bias[c + 1];
            #pragma unroll
            for (int half = 0; half < 2; half++) {
                const int row = r0 + mbase + tm * 16 + grp + half * 8;
                float2 o;
                o.x = C[tm][tn][half * 2 + 0] + bs0;
                o.y = C[tm][tn][half * 2 + 1] + bs1;
                if (KQV) {
                    o.x = to_tf32(o.x); o.y = to_tf32(o.y);
                    const int h = c / E3;
                    const int e = c - h * E3;
                    const int b = row >> 11, n = row & 2047;
                    *(float2*)&g_kqv[(((size_t)(b * Hc + h)) * Nc + n) * E3 + e] = o;
                } else {
                    *(float2*)&outp[(size_t)row * Dc + c] = o;
                }
            }
        }
    }
}

// ---------------------------------------------------------------------------
// Attention: flash, 64x64 tile, 4 warps x 16 rows. PAIRED SCHEDULING:
// each CTA processes q-tiles (31-p) then (p) -> uniform 33 tile-units per
// CTA, 512 CTAs total = one flat wave (no causal-imbalance tail).
// ---------------------------------------------------------------------------
#define ATTN_SMEM 53248
__global__ __launch_bounds__(128) void attn_mma()
{
    extern __shared__ float sm[];
    float* Ks  = sm;           // stride 68
    float* QPs = sm + 4352;    // stride 68 (Q staged, then P per-warp bands)
    float* Vs  = sm + 8704;    // stride 72

    const int t = threadIdx.x;
    const int lane = t & 31, warp = t >> 5;
    const int grp = lane >> 2, ctg = lane & 3;
    const int mb = warp * 16;
    const int bh = blockIdx.y;
    const int b = bh >> 4, h = bh & 15;
    const int p = blockIdx.x;          // 0..15
    const float* base = g_kqv + (size_t)bh * Nc * E3;

    #pragma unroll 1
    for (int seg = 0; seg < 2; seg++) {
        const int qt = seg == 0 ? (31 - p) : p;
        const int q0 = qt * 64;

        __syncthreads();   // QPs free (prev segment fully done)
        #pragma unroll
        for (int it = 0; it < 8; it++) {
            int task = it * 128 + t;
            int c = task >> 4, d4 = (task & 15) * 4;
            float4 v = *(const float4*)&base[(size_t)(q0 + c) * E3 + 64 + d4];
            v.x *= 0.125f; v.y *= 0.125f; v.z *= 0.125f; v.w *= 0.125f;
            *(float4*)&QPs[c * 68 + d4] = v;
        }
        __syncthreads();
        uint32_t qf[8][4];
        #pragma unroll
        for (int kk = 0; kk < 8; kk++) {
            qf[kk][0] = __float_as_uint(QPs[(mb + grp) * 68 + kk * 8 + ctg]);
            qf[kk][1] = __float_as_uint(QPs[(mb + grp + 8) * 68 + kk * 8 + ctg]);
            qf[kk][2] = __float_as_uint(QPs[(mb + grp) * 68 + kk * 8 + ctg + 4]);
            qf[kk][3] = __float_as_uint(QPs[(mb + grp + 8) * 68 + kk * 8 + ctg + 4]);
        }

        float OC[8][4];
        #pragma unroll
        for (int i = 0; i < 8; i++)
            #pragma unroll
            for (int j = 0; j < 4; j++) OC[i][j] = 0.f;
        float m0 = -1e30f, m1 = -1e30f, l0 = 0.f, l1 = 0.f;

        for (int kt = 0; kt <= qt; kt++) {
            const int k0 = kt * 64;
            __syncthreads();
            #pragma unroll
            for (int it = 0; it < 8; it++) {
                int task = it * 128 + t;
                int c = task >> 4, d4 = (task & 15) * 4;
                float4 v = *(const float4*)&base[(size_t)(k0 + c) * E3 + d4];
                *(float4*)&Ks[c * 68 + d4] = v;
            }
            #pragma unroll
            for (int it = 0; it < 8; it++) {
                int task = it * 128 + t;
                int c = task >> 4, d4 = (task & 15) * 4;
                float4 v = *(const float4*)&base[(size_t)(k0 + c) * E3 + 128 + d4];
                *(float4*)&Vs[c * 72 + d4] = v;
            }
            __syncthreads();

            float SC[8][4];
            #pragma unroll
            for (int i = 0; i < 8; i++)
                #pragma unroll
                for (int j = 0; j < 4; j++) SC[i][j] = 0.f;
            #pragma unroll
            for (int kk = 0; kk < 8; kk++) {
                #pragma unroll
                for (int nt = 0; nt < 8; nt++) {
                    uint32_t bf[2];
                    bf[0] = __float_as_uint(Ks[(nt * 8 + grp) * 68 + kk * 8 + ctg]);
                    bf[1] = __float_as_uint(Ks[(nt * 8 + grp) * 68 + kk * 8 + ctg + 4]);
                    mma_tf32(SC[nt], qf[kk], bf);
                }
            }

            if (kt == qt) {
                const int r0l = mb + grp, r1l = mb + grp + 8;
                #pragma unroll
                for (int nt = 0; nt < 8; nt++) {
                    const int col = nt * 8 + 2 * ctg;
                    if (col > r0l)     SC[nt][0] = -1e30f;
                    if (col + 1 > r0l) SC[nt][1] = -1e30f;
                    if (col > r1l)     SC[nt][2] = -1e30f;
                    if (col + 1 > r1l) SC[nt][3] = -1e30f;
                }
            }

            float tm0 = -1e30f, tm1 = -1e30f;
            #pragma unroll
            for (int nt = 0; nt < 8; nt++) {
                tm0 = fmaxf(tm0, fmaxf(SC[nt][0], SC[nt][1]));
                tm1 = fmaxf(tm1, fmaxf(SC[nt][2], SC[nt][3]));
            }
            tm0 = fmaxf(tm0, __shfl_xor_sync(0xffffffffu, tm0, 1));
            tm0 = fmaxf(tm0, __shfl_xor_sync(0xffffffffu, tm0, 2));
            tm1 = fmaxf(tm1, __shfl_xor_sync(0xffffffffu, tm1, 1));
            tm1 = fmaxf(tm1, __shfl_xor_sync(0xffffffffu, tm1, 2));
            const float mn0 = fmaxf(m0, tm0), mn1 = fmaxf(m1, tm1);
            const float corr0 = __expf(m0 - mn0), corr1 = __expf(m1 - mn1);
            m0 = mn0; m1 = mn1;
            float s0 = 0.f, s1 = 0.f;
            #pragma unroll
            for (int nt = 0; nt < 8; nt++) {
                SC[nt][0] = __expf(SC[nt][0] - mn0); s0 += SC[nt][0];
                SC[nt][1] = __expf(SC[nt][1] - mn0); s0 += SC[nt][1];
                SC[nt][2] = __expf(SC[nt][2] - mn1); s1 += SC[nt][2];
                SC[nt][3] = __expf(SC[nt][3] - mn1); s1 += SC[nt][3];
            }
            s0 += __shfl_xor_sync(0xffffffffu, s0, 1);
            s0 += __shfl_xor_sync(0xffffffffu, s0, 2);
            s1 += __shfl_xor_sync(0xffffffffu, s1, 1);
            s1 += __shfl_xor_sync(0xffffffffu, s1, 2);
            l0 = l0 * corr0 + s0;
            l1 = l1 * corr1 + s1;
            #pragma unroll
            for (int nt = 0; nt < 8; nt++) {
                OC[nt][0] *= corr0; OC[nt][1] *= corr0;
                OC[nt][2] *= corr1; OC[nt][3] *= corr1;
            }

            #pragma unroll
            for (int nt = 0; nt < 8; nt++) {
                float2 p0, p1;
                p0.x = to_tf32(SC[nt][0]); p0.y = to_tf32(SC[nt][1]);
                p1.x = to_tf32(SC[nt][2]); p1.y = to_tf32(SC[nt][3]);
                *(float2*)&QPs[(mb + grp) * 68 + nt * 8 + 2 * ctg] = p0;
                *(float2*)&QPs[(mb + grp + 8) * 68 + nt * 8 + 2 * ctg] = p1;
            }
            __syncwarp();

            #pragma unroll
            for (int kk = 0; kk < 8; kk++) {
                uint32_t af[4];
                af[0] = __float_as_uint(QPs[(mb + grp) * 68 + kk * 8 + ctg]);
                af[1] = __float_as_uint(QPs[(mb + grp + 8) * 68 + kk * 8 + ctg]);
                af[2] = __float_as_uint(QPs[(mb + grp) * 68 + kk * 8 + ctg + 4]);
                af[3] = __float_as_uint(QPs[(mb + grp + 8) * 68 + kk * 8 + ctg + 4]);
                #pragma unroll
                for (int dt = 0; dt < 8; dt++) {
                    uint32_t bf[2];
                    bf[0] = __float_as_uint(Vs[(kk * 8 + ctg) * 72 + dt * 8 + grp]);
                    bf[1] = __float_as_uint(Vs[(kk * 8 + ctg + 4) * 72 + dt * 8 + grp]);
                    mma_tf32(OC[dt], af, bf);
                }
            }
        }

        const float inv0 = 1.f / l0, inv1 = 1.f / l1;
        const int r0g = b * Nc + q0 + mb + grp;
        #pragma unroll
        for (int dt = 0; dt < 8; dt++) {
            const int c = h * 64 + dt * 8 + 2 * ctg;
            float2 o0, o1;
            o0.x = to_tf32(OC[dt][0] * inv0); o0.y = to_tf32(OC[dt][1] * inv0);
            o1.x = to_tf32(OC[dt][2] * inv1); o1.y = to_tf32(OC[dt][3] * inv1);
            *(float2*)&g_sa[(size_t)r0g * Dc + c] = o0;
            *(float2*)&g_sa[(size_t)(r0g + 8) * Dc + c] = o1;
        }
    }
}

extern "C" void kernel_launch(void* const* d_in, const int* in_sizes, int n_in,
                              void* d_out, int out_size)
{
    const float* x  = (const float*)d_in[0];
    const float* Wk = (const float*)d_in[1];
    const float* bk = (const float*)d_in[2];
    const float* Wp = (const float*)d_in[3];
    const float* bp = (const float*)d_in[4];
    float* out = (float*)d_out;

    cudaFuncSetAttribute((const void*)gemm_mma<true>,
                         cudaFuncAttributeMaxDynamicSharedMemorySize, GSMEM);
    cudaFuncSetAttribute((const void*)gemm_mma<false>,
                         cudaFuncAttributeMaxDynamicSharedMemorySize, GSMEM);
    cudaFuncSetAttribute((const void*)attn_mma,
                         cudaFuncAttributeMaxDynamicSharedMemorySize, ATTN_SMEM);

    prepass<<<8192, 256>>>(x, Wp, Wk);

    gemm_mma<true><<<dim3(24, 32), 128, GSMEM>>>(bk, nullptr);

    attn_mma<<<dim3(16, 32), 128, ATTN_SMEM>>>();

    gemm_mma<false><<<dim3(8, 32), 128, GSMEM>>>(bp, out);
}

// round 16
// speedup vs baseline: 1.9173x; 1.7825x over previous
#include <cuda_runtime.h>
#include <cuda_fp16.h>
#include <cstdint>
#include <math.h>

#define Bc 2
#define Nc 2048
#define Dc 1024
#define Hc 16
#define E3 192   // kqv col space per head: k(0:64), q(64:128), v(128:192)

__device__ __half g_kqv16[Bc * Hc * Nc * 128];  // [b,h,n,128]: k(0:64), q(64:128)
__device__ __half g_v16[Bc * Hc * 64 * Nc];     // [b,h,dim,n]  (V transposed)
__device__ __half g_sa16[Bc * Nc * Dc];         // [b,n,d]
__device__ __half g_WkT16[Hc * E3 * Dc];        // W_kqv as [c=h*192+e][k]
__device__ __half g_x16[Bc * Nc * Dc];          // x
__device__ __half g_Wp16[Dc * Dc];              // W_proj

__device__ __forceinline__ uint32_t smem_to_u32(const void* p) {
    uint32_t a;
    asm("{ .reg .u64 t; cvta.to.shared.u64 t, %1; cvt.u32.u64 %0, t; }"
        : "=r"(a) : "l"(p));
    return a;
}
__device__ __forceinline__ uint32_t h2_as_u32(__half2 h) {
    return *reinterpret_cast<uint32_t*>(&h);
}
__device__ __forceinline__ void mma_f16(float* c, const uint32_t* a, const uint32_t* b) {
    asm volatile(
        "mma.sync.aligned.m16n8k16.row.col.f32.f16.f16.f32 "
        "{%0,%1,%2,%3}, {%4,%5,%6,%7}, {%8,%9}, {%0,%1,%2,%3};"
        : "+f"(c[0]), "+f"(c[1]), "+f"(c[2]), "+f"(c[3])
        : "r"(a[0]), "r"(a[1]), "r"(a[2]), "r"(a[3]), "r"(b[0]), "r"(b[1]));
}
#define CP16(dst_u32, src_ptr) \
    asm volatile("cp.async.cg.shared.global [%0], [%1], 16;" \
        :: "r"(dst_u32), "l"(src_ptr))
#define CP_COMMIT() asm volatile("cp.async.commit_group;" ::: "memory")
#define CP_WAIT1()  asm volatile("cp.async.wait_group 1;" ::: "memory")
#define CP_WAIT0()  asm volatile("cp.async.wait_group 0;" ::: "memory")

// ---------------------------------------------------------------------------
// Fused pre-pass: convert x, Wp to half; transpose+convert Wk.
// blocks [0,4096): x ; [4096,5120): Wp ; [5120,8192): Wk transpose.
// ---------------------------------------------------------------------------
__global__ __launch_bounds__(256) void prepass(
    const float* __restrict__ x, const float* __restrict__ Wp,
    const float* __restrict__ Wk)
{
    __shared__ float tile[32][33];
    const int bid = blockIdx.x;
    if (bid < 4096) {
        const int i = (bid * 256 + threadIdx.x) * 4;
        float4 v = *(const float4*)&x[i];
        __half2* dst = (__half2*)&g_x16[i];
        dst[0] = __floats2half2_rn(v.x, v.y);
        dst[1] = __floats2half2_rn(v.z, v.w);
    } else if (bid < 5120) {
        const int i = ((bid - 4096) * 256 + threadIdx.x) * 4;
        float4 v = *(const float4*)&Wp[i];
        __half2* dst = (__half2*)&g_Wp16[i];
        dst[0] = __floats2half2_rn(v.x, v.y);
        dst[1] = __floats2half2_rn(v.z, v.w);
    } else {
        const int idx = bid - 5120;          // 0..3071
        const int e0 = (idx % 6) * 32;
        const int k0 = ((idx / 6) % 32) * 32;
        const int h  = idx / 192;
        const float* src = Wk + (size_t)h * Dc * E3;
        __half* dst = g_WkT16 + (size_t)h * E3 * Dc;
        const int tx = threadIdx.x & 31, ty0 = threadIdx.x >> 5;
        #pragma unroll
        for (int i = 0; i < 4; i++) {
            int ty = ty0 + i * 8;
            tile[ty][tx] = src[(size_t)(k0 + ty) * E3 + e0 + tx];
        }
        __syncthreads();
        #pragma unroll
        for (int i = 0; i < 4; i++) {
            int ty = ty0 + i * 8;
            dst[(size_t)(e0 + ty) * Dc + k0 + tx] = __float2half_rn(tile[tx][ty]);
        }
    }
}

// ---------------------------------------------------------------------------
// fp16 mma.sync GEMM: 128x128 CTA tile, 4 warps (2x2), warp tile 64x64.
// K-slab 64 halfs (16 slabs), 2-stage cp.async. m16n8k16, fp32 accum.
// Smem row stride 36 words (4 mod 32 -> fragment bank 4*grp+ctg, conflict-free).
// KQV=true : A=g_x16, B=g_WkT16, out -> g_kqv16 (k,q) + g_v16 (v transposed)
// KQV=false: A=g_sa16, B=g_Wp16, out fp32 row-major + bias
// ---------------------------------------------------------------------------
#define GS2 36                    // words (half2) per row
#define GSTGW (128 * GS2 * 2)     // words per stage (A + B) = 9216
#define GSMEM (2 * GSTGW * 4)     // 73728 B
template<bool KQV>
__global__ __launch_bounds__(128) void gemm_mma(
    const float* __restrict__ bias, float* __restrict__ outp)
{
    const __half* __restrict__ A    = KQV ? (const __half*)g_x16 : (const __half*)g_sa16;
    const __half* __restrict__ Bmat = KQV ? (const __half*)g_WkT16 : (const __half*)g_Wp16;

    extern __shared__ uint32_t smw[];
    const uint32_t su = smem_to_u32(smw);
    const int t = threadIdx.x;
    const int lane = t & 31;
    const int warp = t >> 5;           // 0..3
    const int mbase = (warp >> 1) * 64;
    const int nbase = (warp & 1) * 64;
    const int grp = lane >> 2;
    const int ctg = lane & 3;
    const int c0 = blockIdx.x * 128;
    const int r0 = blockIdx.y * 128;

    auto issue_slab = [&](int s, int buf) {
        const int k0 = s * 64;
        #pragma unroll
        for (int it = 0; it < 8; it++) {
            const int task = it * 128 + t;
            const int row = task >> 3, ch = task & 7;   // 8 x 16B chunks per row
            CP16(su + (uint32_t)(buf * GSTGW + row * GS2 + ch * 4) * 4,
                 &A[(size_t)(r0 + row) * Dc + k0 + ch * 8]);
            CP16(su + (uint32_t)(buf * GSTGW + 128 * GS2 + row * GS2 + ch * 4) * 4,
                 &Bmat[(size_t)(c0 + row) * Dc + k0 + ch * 8]);
        }
    };

    issue_slab(0, 0); CP_COMMIT();
    issue_slab(1, 1); CP_COMMIT();

    float C[4][8][4];
    #pragma unroll
    for (int i = 0; i < 4; i++)
        #pragma unroll
        for (int j = 0; j < 8; j++)
            #pragma unroll
            for (int k = 0; k < 4; k++) C[i][j][k] = 0.f;

    for (int s = 0; s < 16; s++) {
        if (s == 15) { CP_WAIT0(); } else { CP_WAIT1(); }
        __syncthreads();
        const uint32_t* As = smw + (s & 1) * GSTGW;
        const uint32_t* Bs = As + 128 * GS2;
        #pragma unroll
        for (int kk = 0; kk < 4; kk++) {           // 4 x k16 chunks
            const int kof = kk * 8 + ctg;
            uint32_t af[4][4];
            #pragma unroll
            for (int tm = 0; tm < 4; tm++) {
                const int m = mbase + tm * 16 + grp;
                af[tm][0] = As[m * GS2 + kof];
                af[tm][1] = As[(m + 8) * GS2 + kof];
                af[tm][2] = As[m * GS2 + kof + 4];
                af[tm][3] = As[(m + 8) * GS2 + kof + 4];
            }
            #pragma unroll
            for (int tn = 0; tn < 8; tn++) {
                const int n = nbase + tn * 8 + grp;
                uint32_t bf[2];
                bf[0] = Bs[n * GS2 + kof];
                bf[1] = Bs[n * GS2 + kof + 4];
                #pragma unroll
                for (int tm = 0; tm < 4; tm++)
                    mma_f16(C[tm][tn], af[tm], bf);
            }
        }
        __syncthreads();
        if (s + 2 < 16) issue_slab(s + 2, s & 1);
        CP_COMMIT();
    }

    // Epilogue: C rows grp/grp+8, cols 2*ctg, 2*ctg+1
    #pragma unroll
    for (int tm = 0; tm < 4; tm++) {
        #pragma unroll
        for (int tn = 0; tn < 8; tn++) {
            const int c = c0 + nbase + tn * 8 + ctg * 2;
            const float bs0 = bias[c], bs1 = bias[c + 1];
            #pragma unroll
            for (int half_ = 0; half_ < 2; half_++) {
                const int row = r0 + mbase + tm * 16 + grp + half_ * 8;
                float ox = C[tm][tn][half_ * 2 + 0] + bs0;
                float oy = C[tm][tn][half_ * 2 + 1] + bs1;
                if (KQV) {
                    const int h = c / E3;
                    const int e = c - h * E3;
                    const int b = row >> 11, n = row & 2047;
                    if (e < 128) {
                        *(__half2*)&g_kqv16[(((size_t)(b * Hc + h)) * Nc + n) * 128 + e] =
                            __floats2half2_rn(ox, oy);
                    } else {
                        const int d = e - 128;
                        __half* vp = g_v16 + (((size_t)(b * Hc + h)) * 64 + d) * Nc + n;
                        vp[0]  = __float2half_rn(ox);
                        vp[Nc] = __float2half_rn(oy);
                    }
                } else {
                    float2 o; o.x = ox; o.y = oy;
                    *(float2*)&outp[(size_t)row * Dc + c] = o;
                }
            }
        }
    }
}

// ---------------------------------------------------------------------------
// fp16 attention: flash, 64x64 tile, 4 warps x 16 q-rows, m16n8k16.
// Paired scheduling (31-p then p) -> uniform work per CTA.
// Smem (uint32 words): Qs@0, Ks@2304, VT@4608 ([dim][key]), Ps@6912; 36864B.
// ---------------------------------------------------------------------------
#define AS2 36
#define ATTN_SMEM 36864
__global__ __launch_bounds__(128) void attn_mma()
{
    extern __shared__ uint32_t smw[];
    uint32_t* Qs = smw;
    uint32_t* Ks = smw + 2304;
    uint32_t* VT = smw + 4608;
    uint32_t* Ps = smw + 6912;

    const int t = threadIdx.x;
    const int lane = t & 31, warp = t >> 5;
    const int grp = lane >> 2, ctg = lane & 3;
    const int mb = warp * 16;
    const int bh = blockIdx.y;
    const int b = bh >> 4, h = bh & 15;
    const int p = blockIdx.x;          // 0..15
    const __half* kqbase = g_kqv16 + (size_t)bh * Nc * 128;
    const __half* vbase  = g_v16 + (size_t)bh * 64 * Nc;

    #pragma unroll 1
    for (int seg = 0; seg < 2; seg++) {
        const int qt = seg == 0 ? (31 - p) : p;
        const int q0 = qt * 64;

        __syncthreads();
        // stage Q [qrow][dim]
        #pragma unroll
        for (int it = 0; it < 4; it++) {
            const int task = it * 128 + t;
            const int row = task >> 3, ch = task & 7;
            *(uint4*)&Qs[row * AS2 + ch * 4] =
                *(const uint4*)&kqbase[(size_t)(q0 + row) * 128 + 64 + ch * 8];
        }
        __syncthreads();
        uint32_t qf[4][4];
        #pragma unroll
        for (int kk = 0; kk < 4; kk++) {
            qf[kk][0] = Qs[(mb + grp) * AS2 + kk * 8 + ctg];
            qf[kk][1] = Qs[(mb + grp + 8) * AS2 + kk * 8 + ctg];
            qf[kk][2] = Qs[(mb + grp) * AS2 + kk * 8 + ctg + 4];
            qf[kk][3] = Qs[(mb + grp + 8) * AS2 + kk * 8 + ctg + 4];
        }

        float OC[8][4];
        #pragma unroll
        for (int i = 0; i < 8; i++)
            #pragma unroll
            for (int j = 0; j < 4; j++) OC[i][j] = 0.f;
        float m0 = -1e30f, m1 = -1e30f, l0 = 0.f, l1 = 0.f;

        for (int kt = 0; kt <= qt; kt++) {
            const int k0 = kt * 64;
            __syncthreads();
            #pragma unroll
            for (int it = 0; it < 4; it++) {   // K [key][dim]
                const int task = it * 128 + t;
                const int row = task >> 3, ch = task & 7;
                *(uint4*)&Ks[row * AS2 + ch * 4] =
                    *(const uint4*)&kqbase[(size_t)(k0 + row) * 128 + ch * 8];
            }
            #pragma unroll
            for (int it = 0; it < 4; it++) {   // V^T [dim][key]
                const int task = it * 128 + t;
                const int row = task >> 3, ch = task & 7;
                *(uint4*)&VT[row * AS2 + ch * 4] =
                    *(const uint4*)&vbase[(size_t)row * Nc + k0 + ch * 8];
            }
            __syncthreads();

            // S = Q K^T, then scale by 1/8 in fp32
            float SC[8][4];
            #pragma unroll
            for (int i = 0; i < 8; i++)
                #pragma unroll
                for (int j = 0; j < 4; j++) SC[i][j] = 0.f;
            #pragma unroll
            for (int kk = 0; kk < 4; kk++) {
                #pragma unroll
                for (int nt = 0; nt < 8; nt++) {
                    uint32_t bf[2];
                    bf[0] = Ks[(nt * 8 + grp) * AS2 + kk * 8 + ctg];
                    bf[1] = Ks[(nt * 8 + grp) * AS2 + kk * 8 + ctg + 4];
                    mma_f16(SC[nt], qf[kk], bf);
                }
            }
            #pragma unroll
            for (int i = 0; i < 8; i++)
                #pragma unroll
                for (int j = 0; j < 4; j++) SC[i][j] *= 0.125f;

            if (kt == qt) {
                const int r0l = mb + grp, r1l = mb + grp + 8;
                #pragma unroll
                for (int nt = 0; nt < 8; nt++) {
                    const int col = nt * 8 + 2 * ctg;
                    if (col > r0l)     SC[nt][0] = -1e30f;
                    if (col + 1 > r0l) SC[nt][1] = -1e30f;
                    if (col > r1l)     SC[nt][2] = -1e30f;
                    if (col + 1 > r1l) SC[nt][3] = -1e30f;
                }
            }

            float tm0 = -1e30f, tm1 = -1e30f;
            #pragma unroll
            for (int nt = 0; nt < 8; nt++) {
                tm0 = fmaxf(tm0, fmaxf(SC[nt][0], SC[nt][1]));
                tm1 = fmaxf(tm1, fmaxf(SC[nt][2], SC[nt][3]));
            }
            tm0 = fmaxf(tm0, __shfl_xor_sync(0xffffffffu, tm0, 1));
            tm0 = fmaxf(tm0, __shfl_xor_sync(0xffffffffu, tm0, 2));
            tm1 = fmaxf(tm1, __shfl_xor_sync(0xffffffffu, tm1, 1));
            tm1 = fmaxf(tm1, __shfl_xor_sync(0xffffffffu, tm1, 2));
            const float mn0 = fmaxf(m0, tm0), mn1 = fmaxf(m1, tm1);
            const float corr0 = __expf(m0 - mn0), corr1 = __expf(m1 - mn1);
            m0 = mn0; m1 = mn1;
            float s0 = 0.f, s1 = 0.f;
            #pragma unroll
            for (int nt = 0; nt < 8; nt++) {
                SC[nt][0] = __expf(SC[nt][0] - mn0); s0 += SC[nt][0];
                SC[nt][1] = __expf(SC[nt][1] - mn0); s0 += SC[nt][1];
                SC[nt][2] = __expf(SC[nt][2] - mn1); s1 += SC[nt][2];
                SC[nt][3] = __expf(SC[nt][3] - mn1); s1 += SC[nt][3];
            }
            s0 += __shfl_xor_sync(0xffffffffu, s0, 1);
            s0 += __shfl_xor_sync(0xffffffffu, s0, 2);
            s1 += __shfl_xor_sync(0xffffffffu, s1, 1);
            s1 += __shfl_xor_sync(0xffffffffu, s1, 2);
            l0 = l0 * corr0 + s0;
            l1 = l1 * corr1 + s1;
            #pragma unroll
            for (int nt = 0; nt < 8; nt++) {
                OC[nt][0] *= corr0; OC[nt][1] *= corr0;
                OC[nt][2] *= corr1; OC[nt][3] *= corr1;
            }

            // P -> warp-private band of Ps (half2 pairs along key dim)
            #pragma unroll
            for (int nt = 0; nt < 8; nt++) {
                Ps[(mb + grp) * AS2 + nt * 4 + ctg] =
                    h2_as_u32(__floats2half2_rn(SC[nt][0], SC[nt][1]));
                Ps[(mb + grp + 8) * AS2 + nt * 4 + ctg] =
                    h2_as_u32(__floats2half2_rn(SC[nt][2], SC[nt][3]));
            }
            __syncwarp();

            // O += P V : A = P[qrow][key], B = VT[n=dim][k=key]
            #pragma unroll
            for (int kc = 0; kc < 4; kc++) {
                uint32_t af[4];
                af[0] = Ps[(mb + grp) * AS2 + kc * 8 + ctg];
                af[1] = Ps[(mb + grp + 8) * AS2 + kc * 8 + ctg];
                af[2] = Ps[(mb + grp) * AS2 + kc * 8 + ctg + 4];
                af[3] = Ps[(mb + grp + 8) * AS2 + kc * 8 + ctg + 4];
                #pragma unroll
                for (int dt = 0; dt < 8; dt++) {
                    uint32_t bf[2];
                    bf[0] = VT[(dt * 8 + grp) * AS2 + kc * 8 + ctg];
                    bf[1] = VT[(dt * 8 + grp) * AS2 + kc * 8 + ctg + 4];
                    mma_f16(OC[dt], af, bf);
                }
            }
        }

        const float inv0 = 1.f / l0, inv1 = 1.f / l1;
        const int r0g = b * Nc + q0 + mb + grp;
        #pragma unroll
        for (int dt = 0; dt < 8; dt++) {
            const int c = h * 64 + dt * 8 + 2 * ctg;
            *(__half2*)&g_sa16[(size_t)r0g * Dc + c] =
                __floats2half2_rn(OC[dt][0] * inv0, OC[dt][1] * inv0);
            *(__half2*)&g_sa16[(size_t)(r0g + 8) * Dc + c] =
                __floats2half2_rn(OC[dt][2] * inv1, OC[dt][3] * inv1);
        }
    }
}

extern "C" void kernel_launch(void* const* d_in, const int* in_sizes, int n_in,
                              void* d_out, int out_size)
{
    const float* x  = (const float*)d_in[0];
    const float* Wk = (const float*)d_in[1];
    const float* bk = (const float*)d_in[2];
    const float* Wp = (const float*)d_in[3];
    const float* bp = (const float*)d_in[4];
    float* out = (float*)d_out;

    cudaFuncSetAttribute((const void*)gemm_mma<true>,
                         cudaFuncAttributeMaxDynamicSharedMemorySize, GSMEM);
    cudaFuncSetAttribute((const void*)gemm_mma<false>,
                         cudaFuncAttributeMaxDynamicSharedMemorySize, GSMEM);
    cudaFuncSetAttribute((const void*)attn_mma,
                         cudaFuncAttributeMaxDynamicSharedMemorySize, ATTN_SMEM);

    prepass<<<8192, 256>>>(x, Wp, Wk);

    gemm_mma<true><<<dim3(24, 32), 128, GSMEM>>>(bk, nullptr);

    attn_mma<<<dim3(16, 32), 128, ATTN_SMEM>>>();

    gemm_mma<false><<<dim3(8, 32), 128, GSMEM>>>(bp, out);
}